// round 1
// baseline (speedup 1.0000x reference)
#include <cuda_runtime.h>
#include <math.h>

#define Bsz    2048
#define Hd     256
#define INd    64
#define KTERMS 8
#define ROWS   16           // batch rows per CTA
#define NCTAS  (Bsz/ROWS)   // 128
#define PITCH  20           // smem row pitch in floats (16B-aligned rows)

// Pre-transposed weights (L2-resident scratch; __device__ globals, no allocs)
__device__ float g_whT[Hd*Hd];     // whT[j*Hd+k]   = wh[k*Hd+j]
__device__ float g_woutT[Hd*Hd];   // woutT[k*Hd+h] = wout[h*Hd+k]
__device__ float g_wxT[INd*Hd];    // wxT[i*Hd+k]   = wx[k*INd+i]

// ---------------- packed f32x2 helpers (sm_103a FFMA2 path) ----------------
__device__ __forceinline__ unsigned long long pack2(float lo, float hi) {
    unsigned long long r;
    asm("mov.b64 %0, {%1,%2};" : "=l"(r) : "f"(lo), "f"(hi));
    return r;
}
__device__ __forceinline__ void unpack2(unsigned long long v, float& lo, float& hi) {
    asm("mov.b64 {%0,%1}, %2;" : "=f"(lo), "=f"(hi) : "l"(v));
}
__device__ __forceinline__ unsigned long long fma2(unsigned long long a,
                                                   unsigned long long b,
                                                   unsigned long long c) {
    unsigned long long d;
    asm("fma.rn.f32x2 %0, %1, %2, %3;" : "=l"(d) : "l"(a), "l"(b), "l"(c));
    return d;
}
__device__ __forceinline__ unsigned long long mul2(unsigned long long a,
                                                   unsigned long long b) {
    unsigned long long d;
    asm("mul.rn.f32x2 %0, %1, %2;" : "=l"(d) : "l"(a), "l"(b));
    return d;
}
__device__ __forceinline__ unsigned long long add2(unsigned long long a,
                                                   unsigned long long b) {
    unsigned long long d;
    asm("add.rn.f32x2 %0, %1, %2;" : "=l"(d) : "l"(a), "l"(b));
    return d;
}

// ---------------- transpose: out[c*rows + r] = in[r*cols + c] ----------------
// which: 0 -> g_whT, 1 -> g_woutT, 2 -> g_wxT. All dims multiples of 32.
__global__ void transpose_kernel(const float* __restrict__ in, int rows, int cols, int which) {
    __shared__ float tile[32][33];
    float* out = (which == 0) ? g_whT : (which == 1) ? g_woutT : g_wxT;
    int c0 = blockIdx.x * 32, r0 = blockIdx.y * 32;
    #pragma unroll
    for (int dy = threadIdx.y; dy < 32; dy += 8) {
        tile[dy][threadIdx.x] = in[(r0 + dy) * cols + (c0 + threadIdx.x)];
    }
    __syncthreads();
    #pragma unroll
    for (int dy = threadIdx.y; dy < 32; dy += 8) {
        out[(c0 + dy) * rows + (r0 + threadIdx.x)] = tile[threadIdx.x][dy];
    }
}

// acc[q] covers rows (2q, 2q+1). For all j: acc += Wt[j][k] * sIn[j][rows]
__device__ __forceinline__ void gemm256(const float* __restrict__ Wt, int k,
                                        const float* sIn, unsigned long long acc[8]) {
#pragma unroll 8
    for (int j = 0; j < Hd; ++j) {
        float w = Wt[j * Hd + k];
        unsigned long long ww = pack2(w, w);
        const ulonglong2* rp = reinterpret_cast<const ulonglong2*>(sIn + j * PITCH);
        #pragma unroll
        for (int q2 = 0; q2 < 4; ++q2) {
            ulonglong2 v = rp[q2];
            acc[2*q2]     = fma2(ww, v.x, acc[2*q2]);
            acc[2*q2 + 1] = fma2(ww, v.y, acc[2*q2 + 1]);
        }
    }
}

// ---------------- fused vector-field kernel: one launch does everything ----------------
__global__ void __launch_bounds__(256, 1)
fused_kernel(const float* __restrict__ hin, const float* __restrict__ xin,
             const float* __restrict__ xdin, const float* __restrict__ b0,
             const float* __restrict__ b1, float* __restrict__ out) {
    __shared__ __align__(16) float sA[Hd * PITCH];  // 20 KB
    __shared__ __align__(16) float sB[Hd * PITCH];  // 20 KB
    const int k = threadIdx.x;               // output feature index owned by this thread
    const int row0 = blockIdx.x * ROWS;      // first batch row of this CTA

    // ---- stage inputs transposed into smem: sA[j][r] = h, sB[i][r] = x, sB[64+i][r] = xdot
    #pragma unroll
    for (int r = 0; r < ROWS; ++r)
        sA[k * PITCH + r] = hin[(row0 + r) * Hd + k];
    for (int e = k; e < ROWS * INd; e += 256) {
        int r = e >> 6, i = e & 63;
        sB[i * PITCH + r]         = xin[(row0 + r) * INd + i];
        sB[(INd + i) * PITCH + r] = xdin[(row0 + r) * INd + i];
    }
    __syncthreads();

    // ---- phase 1: l1[r][k] = x.wx[k] + h.wh[k] + b0[k],  u[r][k] = xdot.wx[k]
    unsigned long long l1[8], uu[8];
    {
        float b0k = b0[k];
        unsigned long long b0p = pack2(b0k, b0k);
        #pragma unroll
        for (int q = 0; q < 8; ++q) { l1[q] = b0p; uu[q] = 0ull; }
    }
    #pragma unroll 4
    for (int i = 0; i < INd; ++i) {
        float w = g_wxT[i * Hd + k];
        unsigned long long ww = pack2(w, w);
        const ulonglong2* rx = reinterpret_cast<const ulonglong2*>(sB + i * PITCH);
        const ulonglong2* rd = reinterpret_cast<const ulonglong2*>(sB + (INd + i) * PITCH);
        #pragma unroll
        for (int q2 = 0; q2 < 4; ++q2) {
            ulonglong2 vx = rx[q2], vd = rd[q2];
            l1[2*q2]     = fma2(ww, vx.x, l1[2*q2]);
            l1[2*q2 + 1] = fma2(ww, vx.y, l1[2*q2 + 1]);
            uu[2*q2]     = fma2(ww, vd.x, uu[2*q2]);
            uu[2*q2 + 1] = fma2(ww, vd.y, uu[2*q2 + 1]);
        }
    }
    gemm256(g_whT, k, sA, l1);   // + h @ wh^T
    __syncthreads();             // all reads of sA/sB done

    // gate = (l1>0), relu -> sB, g*u -> sA. gate stays in registers for all 8 iterations.
    unsigned long long gate[8];
    #pragma unroll
    for (int q = 0; q < 8; ++q) {
        float a, bb;  unpack2(l1[q], a, bb);
        float ua, ub; unpack2(uu[q], ua, ub);
        float ga = (a  > 0.f) ? 1.f : 0.f;
        float gb = (bb > 0.f) ? 1.f : 0.f;
        gate[q] = pack2(ga, gb);
        sB[k * PITCH + 2*q]     = ga * a;
        sB[k * PITCH + 2*q + 1] = gb * bb;
        sA[k * PITCH + 2*q]     = ga * ua;
        sA[k * PITCH + 2*q + 1] = gb * ub;
    }
    __syncthreads();

    // ---- phase 2: lout = relu @ wout^T + b1 ; jx = (g*u) @ wout^T ; dtanh, curr=jx*dtanh
    unsigned long long lo[8], jx[8];
    {
        float b1k = b1[k];
        unsigned long long bp = pack2(b1k, b1k);
        #pragma unroll
        for (int q = 0; q < 8; ++q) { lo[q] = bp; jx[q] = 0ull; }
    }
    #pragma unroll 4
    for (int j = 0; j < Hd; ++j) {
        float w = g_woutT[j * Hd + k];
        unsigned long long ww = pack2(w, w);
        const ulonglong2* rr = reinterpret_cast<const ulonglong2*>(sB + j * PITCH);
        const ulonglong2* rg = reinterpret_cast<const ulonglong2*>(sA + j * PITCH);
        #pragma unroll
        for (int q2 = 0; q2 < 4; ++q2) {
            ulonglong2 vr = rr[q2], vg = rg[q2];
            lo[2*q2]     = fma2(ww, vr.x, lo[2*q2]);
            lo[2*q2 + 1] = fma2(ww, vr.y, lo[2*q2 + 1]);
            jx[2*q2]     = fma2(ww, vg.x, jx[2*q2]);
            jx[2*q2 + 1] = fma2(ww, vg.y, jx[2*q2 + 1]);
        }
    }
    __syncthreads();

    unsigned long long dth[8], hdot[8];
    #pragma unroll
    for (int q = 0; q < 8; ++q) {
        float a, bb; unpack2(lo[q], a, bb);
        float ta = tanhf(a), tb = tanhf(bb);
        dth[q] = pack2(1.f - ta * ta, 1.f - tb * tb);
        unsigned long long c = mul2(jx[q], dth[q]);    // curr = jx
        hdot[q] = c;
        reinterpret_cast<unsigned long long*>(sA + k * PITCH)[q] = c;  // curr -> sA
    }
    __syncthreads();

    // ---- 8 Jh-power iterations: curr = dtanh * ((g * (curr @ wh^T)) @ wout^T)
    for (int it = 0; it < KTERMS; ++it) {
        unsigned long long acc[8];
        #pragma unroll
        for (int q = 0; q < 8; ++q) acc[q] = 0ull;
        gemm256(g_whT, k, sA, acc);      // t[r][k] = curr . wh[k]
        __syncthreads();
        #pragma unroll
        for (int q = 0; q < 8; ++q)      // gated t -> sB
            reinterpret_cast<unsigned long long*>(sB + k * PITCH)[q] = mul2(acc[q], gate[q]);
        __syncthreads();
        #pragma unroll
        for (int q = 0; q < 8; ++q) acc[q] = 0ull;
        gemm256(g_woutT, k, sB, acc);    // (gated t) @ wout^T
        __syncthreads();
        #pragma unroll
        for (int q = 0; q < 8; ++q) {
            unsigned long long c = mul2(acc[q], dth[q]);
            hdot[q] = add2(hdot[q], c);
            reinterpret_cast<unsigned long long*>(sA + k * PITCH)[q] = c;  // curr -> sA
        }
        __syncthreads();
    }

    // ---- write h_dot (coalesced: fixed r, consecutive k across threads)
    #pragma unroll
    for (int q = 0; q < 8; ++q) {
        float a, bb; unpack2(hdot[q], a, bb);
        out[(row0 + 2*q)     * Hd + k] = a;
        out[(row0 + 2*q + 1) * Hd + k] = bb;
    }
}

extern "C" void kernel_launch(void* const* d_in, const int* in_sizes, int n_in,
                              void* d_out, int out_size) {
    (void)in_sizes; (void)n_in; (void)out_size;
    const float* h_   = (const float*)d_in[0];
    const float* x    = (const float*)d_in[1];
    const float* xdot = (const float*)d_in[2];
    const float* wx   = (const float*)d_in[3];
    const float* wh   = (const float*)d_in[4];
    const float* wout = (const float*)d_in[5];
    const float* b0   = (const float*)d_in[6];
    const float* b1   = (const float*)d_in[7];
    float* out = (float*)d_out;

    transpose_kernel<<<dim3(Hd/32,  Hd/32), dim3(32, 8)>>>(wh,   Hd, Hd,  0);
    transpose_kernel<<<dim3(Hd/32,  Hd/32), dim3(32, 8)>>>(wout, Hd, Hd,  1);
    transpose_kernel<<<dim3(INd/32, Hd/32), dim3(32, 8)>>>(wx,   Hd, INd, 2);
    fused_kernel<<<NCTAS, 256>>>(h_, x, xdot, b0, b1, out);
}

// round 3
// speedup vs baseline: 1.1503x; 1.1503x over previous
#include <cuda_runtime.h>
#include <math.h>

#define Bsz    2048
#define Hd     256
#define INd    64
#define KTERMS 8
#define ROWS   14            // batch rows per CTA (7 f32x2 pairs)
#define NCTAS  147           // ceil(2048/14) -> all SMs busy
#define PITCH  16            // smem row pitch in floats (64B rows)
#define NTHR   512           // two 256-thread j-groups

// Pre-transposed weights (L2-resident scratch)
__device__ float g_whT[Hd*Hd];     // whT[j*Hd+k]   = wh[k*Hd+j]
__device__ float g_woutT[Hd*Hd];   // woutT[j*Hd+k] = wout[k*Hd+j]
__device__ float g_wxT[INd*Hd];    // wxT[i*Hd+k]   = wx[k*INd+i]

// ---------------- packed f32x2 helpers (sm_103a FFMA2) ----------------
__device__ __forceinline__ unsigned long long pack2(float lo, float hi) {
    unsigned long long r;
    asm("mov.b64 %0, {%1,%2};" : "=l"(r) : "f"(lo), "f"(hi));
    return r;
}
__device__ __forceinline__ void unpack2(unsigned long long v, float& lo, float& hi) {
    asm("mov.b64 {%0,%1}, %2;" : "=f"(lo), "=f"(hi) : "l"(v));
}
__device__ __forceinline__ unsigned long long fma2(unsigned long long a,
                                                   unsigned long long b,
                                                   unsigned long long c) {
    unsigned long long d;
    asm("fma.rn.f32x2 %0, %1, %2, %3;" : "=l"(d) : "l"(a), "l"(b), "l"(c));
    return d;
}
__device__ __forceinline__ unsigned long long mul2(unsigned long long a,
                                                   unsigned long long b) {
    unsigned long long d;
    asm("mul.rn.f32x2 %0, %1, %2;" : "=l"(d) : "l"(a), "l"(b));
    return d;
}
__device__ __forceinline__ unsigned long long add2(unsigned long long a,
                                                   unsigned long long b) {
    unsigned long long d;
    asm("add.rn.f32x2 %0, %1, %2;" : "=l"(d) : "l"(a), "l"(b));
    return d;
}

struct Row { unsigned long long v[7]; };
__device__ __forceinline__ Row ldrow(const float* p) {
    Row r;
    const ulonglong2* q = reinterpret_cast<const ulonglong2*>(p);
    ulonglong2 a = q[0], b = q[1], c = q[2];
    r.v[0]=a.x; r.v[1]=a.y; r.v[2]=b.x; r.v[3]=b.y; r.v[4]=c.x; r.v[5]=c.y;
    r.v[6] = reinterpret_cast<const unsigned long long*>(p)[6];
    return r;
}

// partial GEMM over j in [j0,j1): acc[q] += Wt[j][k] * sIn[j][2q..2q+1]
__device__ __forceinline__ void gemm_part(const float* __restrict__ Wt, int k,
                                          const float* sIn, int j0, int j1,
                                          unsigned long long acc[7]) {
#pragma unroll 8
    for (int j = j0; j < j1; ++j) {
        float w = Wt[j * Hd + k];
        unsigned long long ww = pack2(w, w);
        Row v = ldrow(sIn + j * PITCH);
#pragma unroll
        for (int q = 0; q < 7; ++q) acc[q] = fma2(ww, v.v[q], acc[q]);
    }
}

// ---------------- merged transpose (single launch) ----------------
__global__ void transpose_all(const float* __restrict__ wh,
                              const float* __restrict__ wout,
                              const float* __restrict__ wx) {
    __shared__ float tile[32][33];
    int b = blockIdx.x;
    const float* in; float* out; int rows, cols, bx;
    if (b < 64)       { in = wh;   out = g_whT;   rows = Hd; cols = Hd;  bx = b; }
    else if (b < 128) { in = wout; out = g_woutT; rows = Hd; cols = Hd;  bx = b - 64; }
    else              { in = wx;   out = g_wxT;   rows = Hd; cols = INd; bx = b - 128; }
    int nbx = cols / 32;
    int c0 = (bx % nbx) * 32, r0 = (bx / nbx) * 32;
    for (int dy = threadIdx.y; dy < 32; dy += 8)
        tile[dy][threadIdx.x] = in[(r0 + dy) * cols + (c0 + threadIdx.x)];
    __syncthreads();
    for (int dy = threadIdx.y; dy < 32; dy += 8)
        out[(c0 + dy) * rows + (r0 + threadIdx.x)] = tile[threadIdx.x][dy];
}

// ---------------- fused vector-field kernel ----------------
__global__ void __launch_bounds__(NTHR, 1)
fused_kernel(const float* __restrict__ hin, const float* __restrict__ xin,
             const float* __restrict__ xdin, const float* __restrict__ b0,
             const float* __restrict__ b1, float* __restrict__ out) {
    __shared__ __align__(16) float sA[Hd * PITCH];                 // 16 KB
    __shared__ __align__(16) float sB[Hd * PITCH];                 // 16 KB
    __shared__ __align__(16) unsigned long long sRed[Hd * 7];      // 14 KB

    const int tid  = threadIdx.x;
    const int k    = tid & 255;        // feature column owned by this thread
    const int g    = tid >> 8;         // j-group: 0 or 1
    const int row0 = blockIdx.x * ROWS;

    // ---- stage inputs transposed: sA[j][r]=h, sB[i][r]=x, sB[64+i][r]=xdot
    for (int e = tid; e < ROWS * Hd; e += NTHR) {
        int r = e >> 8, j = e & 255;
        sA[j * PITCH + r] = (row0 + r < Bsz) ? hin[(row0 + r) * Hd + j] : 0.f;
    }
    for (int e = tid; e < ROWS * INd; e += NTHR) {
        int r = e >> 6, i = e & 63;
        bool ok = (row0 + r < Bsz);
        sB[i * PITCH + r]         = ok ? xin[(row0 + r) * INd + i]  : 0.f;
        sB[(INd + i) * PITCH + r] = ok ? xdin[(row0 + r) * INd + i] : 0.f;
    }
    __syncthreads();

    // ---- phase 1: l1 = x@wx^T + h@wh^T + b0 ; uu = xdot@wx^T   (j split by group)
    unsigned long long l1[7], uu[7];
#pragma unroll
    for (int q = 0; q < 7; ++q) { l1[q] = 0ull; uu[q] = 0ull; }
    {
        int i0 = g * 32, i1 = i0 + 32;
#pragma unroll 4
        for (int i = i0; i < i1; ++i) {
            float w = g_wxT[i * Hd + k];
            unsigned long long ww = pack2(w, w);
            Row vx = ldrow(sB + i * PITCH);
            Row vd = ldrow(sB + (INd + i) * PITCH);
#pragma unroll
            for (int q = 0; q < 7; ++q) {
                l1[q] = fma2(ww, vx.v[q], l1[q]);
                uu[q] = fma2(ww, vd.v[q], uu[q]);
            }
        }
    }
    gemm_part(g_whT, k, sA, g * 128, g * 128 + 128, l1);

    unsigned long long gate[7];
    if (g == 1) {
#pragma unroll
        for (int q = 0; q < 7; ++q) sRed[k * 7 + q] = l1[q];
    }
    __syncthreads();
    if (g == 0) {
        float b0k = b0[k];
        unsigned long long b0p = pack2(b0k, b0k);
#pragma unroll
        for (int q = 0; q < 7; ++q) {
            l1[q] = add2(add2(l1[q], sRed[k * 7 + q]), b0p);
            float a, bb; unpack2(l1[q], a, bb);
            float ga = (a > 0.f) ? 1.f : 0.f;
            float gb = (bb > 0.f) ? 1.f : 0.f;
            gate[q] = pack2(ga, gb);
            sB[k * PITCH + 2*q]     = ga * a;    // relu -> sB
            sB[k * PITCH + 2*q + 1] = gb * bb;
        }
    }
    __syncthreads();
    if (g == 1) {
#pragma unroll
        for (int q = 0; q < 7; ++q) sRed[k * 7 + q] = uu[q];
    }
    __syncthreads();
    if (g == 0) {
#pragma unroll
        for (int q = 0; q < 7; ++q) {
            unsigned long long u = add2(uu[q], sRed[k * 7 + q]);
            reinterpret_cast<unsigned long long*>(sA + k * PITCH)[q] = mul2(u, gate[q]); // g*u -> sA
        }
    }
    __syncthreads();

    // ---- phase 2: lout = relu@wout^T + b1 ; jx = (g*u)@wout^T
    unsigned long long lo[7], jx[7];
#pragma unroll
    for (int q = 0; q < 7; ++q) { lo[q] = 0ull; jx[q] = 0ull; }
    {
        int j0 = g * 128, j1 = j0 + 128;
#pragma unroll 4
        for (int j = j0; j < j1; ++j) {
            float w = g_woutT[j * Hd + k];
            unsigned long long ww = pack2(w, w);
            Row vr = ldrow(sB + j * PITCH);
            Row vg = ldrow(sA + j * PITCH);
#pragma unroll
            for (int q = 0; q < 7; ++q) {
                lo[q] = fma2(ww, vr.v[q], lo[q]);
                jx[q] = fma2(ww, vg.v[q], jx[q]);
            }
        }
    }
    unsigned long long dth[7], hdot[7];
    if (g == 1) {
#pragma unroll
        for (int q = 0; q < 7; ++q) sRed[k * 7 + q] = lo[q];
    }
    __syncthreads();
    if (g == 0) {
        float b1k = b1[k];
        unsigned long long bp = pack2(b1k, b1k);
#pragma unroll
        for (int q = 0; q < 7; ++q) {
            unsigned long long L = add2(add2(lo[q], sRed[k * 7 + q]), bp);
            float a, bb; unpack2(L, a, bb);
            float ta = tanhf(a), tb = tanhf(bb);
            dth[q] = pack2(1.f - ta * ta, 1.f - tb * tb);
        }
    }
    __syncthreads();
    if (g == 1) {
#pragma unroll
        for (int q = 0; q < 7; ++q) sRed[k * 7 + q] = jx[q];
    }
    __syncthreads();
    if (g == 0) {
#pragma unroll
        for (int q = 0; q < 7; ++q) {
            unsigned long long c = mul2(add2(jx[q], sRed[k * 7 + q]), dth[q]); // curr = jx*dth
            hdot[q] = c;
            reinterpret_cast<unsigned long long*>(sA + k * PITCH)[q] = c;      // curr -> sA
        }
    }
    __syncthreads();

    // ---- 8 Jh-power iterations: curr = dtanh * ((gate * (curr@wh^T)) @ wout^T)
    for (int it = 0; it < KTERMS; ++it) {
        unsigned long long acc[7];
#pragma unroll
        for (int q = 0; q < 7; ++q) acc[q] = 0ull;
        gemm_part(g_whT, k, sA, g * 128, g * 128 + 128, acc);
        if (g == 1) {
#pragma unroll
            for (int q = 0; q < 7; ++q) sRed[k * 7 + q] = acc[q];
        }
        __syncthreads();
        if (g == 0) {
#pragma unroll
            for (int q = 0; q < 7; ++q) {
                unsigned long long t = add2(acc[q], sRed[k * 7 + q]);
                reinterpret_cast<unsigned long long*>(sB + k * PITCH)[q] = mul2(t, gate[q]);
            }
        }
        __syncthreads();
#pragma unroll
        for (int q = 0; q < 7; ++q) acc[q] = 0ull;
        gemm_part(g_woutT, k, sB, g * 128, g * 128 + 128, acc);
        if (g == 1) {
#pragma unroll
            for (int q = 0; q < 7; ++q) sRed[k * 7 + q] = acc[q];
        }
        __syncthreads();
        if (g == 0) {
#pragma unroll
            for (int q = 0; q < 7; ++q) {
                unsigned long long c = mul2(add2(acc[q], sRed[k * 7 + q]), dth[q]);
                hdot[q] = add2(hdot[q], c);
                reinterpret_cast<unsigned long long*>(sA + k * PITCH)[q] = c;
            }
        }
        __syncthreads();
    }

    // ---- write h_dot (group 0, coalesced in k; guard tail rows)
    if (g == 0) {
#pragma unroll
        for (int q = 0; q < 7; ++q) {
            float a, bb; unpack2(hdot[q], a, bb);
            int r0r = row0 + 2 * q;
            if (r0r < Bsz)     out[r0r       * Hd + k] = a;
            if (r0r + 1 < Bsz) out[(r0r + 1) * Hd + k] = bb;
        }
    }
}

extern "C" void kernel_launch(void* const* d_in, const int* in_sizes, int n_in,
                              void* d_out, int out_size) {
    (void)in_sizes; (void)n_in; (void)out_size;
    const float* h_   = (const float*)d_in[0];
    const float* x    = (const float*)d_in[1];
    const float* xdot = (const float*)d_in[2];
    const float* wx   = (const float*)d_in[3];
    const float* wh   = (const float*)d_in[4];
    const float* wout = (const float*)d_in[5];
    const float* b0   = (const float*)d_in[6];
    const float* b1   = (const float*)d_in[7];
    float* out = (float*)d_out;

    transpose_all<<<144, dim3(32, 8)>>>(wh, wout, wx);
    fused_kernel<<<NCTAS, NTHR>>>(h_, x, xdot, b0, b1, out);
}

// round 4
// speedup vs baseline: 1.6655x; 1.4479x over previous
#include <cuda_runtime.h>
#include <math.h>

#define Bsz    2048
#define Hd     256
#define INd    64
#define KTERMS 8
#define ROWS   14            // batch rows per CTA (7 f32x2 pairs)
#define NCTAS  147
#define PITCH  20            // smem row pitch in floats (80B: 16B-aligned, conflict-free)
#define SSTR   10            // u64 stride per sRed column (80B)
#define NTHR   512           // 128 column-pairs x 4 j-groups

typedef unsigned long long ull;

// Pre-transposed weights (L2-resident)
__device__ float g_whT[Hd*Hd];     // whT[j*Hd+k]   = wh[k*Hd+j]
__device__ float g_woutT[Hd*Hd];   // woutT[j*Hd+k] = wout[k*Hd+j]
__device__ float g_wxT[INd*Hd];    // wxT[i*Hd+k]   = wx[k*INd+i]

// ---------------- packed f32x2 helpers ----------------
__device__ __forceinline__ ull pack2(float lo, float hi) {
    ull r; asm("mov.b64 %0, {%1,%2};" : "=l"(r) : "f"(lo), "f"(hi)); return r;
}
__device__ __forceinline__ void unpack2(ull v, float& lo, float& hi) {
    asm("mov.b64 {%0,%1}, %2;" : "=f"(lo), "=f"(hi) : "l"(v));
}
__device__ __forceinline__ ull fma2(ull a, ull b, ull c) {
    ull d; asm("fma.rn.f32x2 %0, %1, %2, %3;" : "=l"(d) : "l"(a), "l"(b), "l"(c)); return d;
}
__device__ __forceinline__ ull mul2(ull a, ull b) {
    ull d; asm("mul.rn.f32x2 %0, %1, %2;" : "=l"(d) : "l"(a), "l"(b)); return d;
}
__device__ __forceinline__ ull add2(ull a, ull b) {
    ull d; asm("add.rn.f32x2 %0, %1, %2;" : "=l"(d) : "l"(a), "l"(b)); return d;
}

struct Row { ull v[7]; };
__device__ __forceinline__ Row ldrow(const float* p) {
    Row r;
    const ulonglong2* q = reinterpret_cast<const ulonglong2*>(p);
    ulonglong2 a = q[0], b = q[1], c = q[2];
    r.v[0]=a.x; r.v[1]=a.y; r.v[2]=b.x; r.v[3]=b.y; r.v[4]=c.x; r.v[5]=c.y;
    r.v[6] = reinterpret_cast<const ull*>(p)[6];
    return r;
}
__device__ __forceinline__ void st7(ull* p, const ull v[7]) {
    ulonglong2* q = reinterpret_cast<ulonglong2*>(p);
    q[0] = make_ulonglong2(v[0], v[1]);
    q[1] = make_ulonglong2(v[2], v[3]);
    q[2] = make_ulonglong2(v[4], v[5]);
    p[6] = v[6];
}
__device__ __forceinline__ void ld7(const ull* p, ull v[7]) {
    const ulonglong2* q = reinterpret_cast<const ulonglong2*>(p);
    ulonglong2 a = q[0], b = q[1], c = q[2];
    v[0]=a.x; v[1]=a.y; v[2]=b.x; v[3]=b.y; v[4]=c.x; v[5]=c.y; v[6]=p[6];
}
// store 7 u64 to an sA/sB row (float base, 16B aligned)
__device__ __forceinline__ void strow(float* p, const ull v[7]) {
    st7(reinterpret_cast<ull*>(p), v);
}

// dual-column partial GEMM: acc{A,B}[q] += Wt[j][c{,+128}] * sIn[j][2q..2q+1]
__device__ __forceinline__ void gemm2(const float* __restrict__ Wt, int c,
                                      const float* sIn, int j0, int j1,
                                      ull accA[7], ull accB[7]) {
#pragma unroll 8
    for (int j = j0; j < j1; ++j) {
        float wa = Wt[j * Hd + c];
        float wb = Wt[j * Hd + c + 128];
        ull wwa = pack2(wa, wa), wwb = pack2(wb, wb);
        Row v = ldrow(sIn + j * PITCH);
#pragma unroll
        for (int q = 0; q < 7; ++q) {
            accA[q] = fma2(wwa, v.v[q], accA[q]);
            accB[q] = fma2(wwb, v.v[q], accB[q]);
        }
    }
}

// export non-owned partials to sRed[3][Hd][SSTR]
__device__ __forceinline__ void export_partials(ull* sRed, int c, int g,
                                                const ull accA[7], const ull accB[7]) {
    if (g == 0) {
        st7(sRed + (0 * Hd + c + 128) * SSTR, accB);
    } else if (g == 1) {
        st7(sRed + (0 * Hd + c) * SSTR, accA);
    } else {
        int s = g - 1;  // 1 or 2
        st7(sRed + (s * Hd + c) * SSTR, accA);
        st7(sRed + (s * Hd + c + 128) * SSTR, accB);
    }
}
// owner thread k: m = own + slot0[k] + slot1[k] + slot2[k]
__device__ __forceinline__ void merge3(const ull* sRed, int k, const ull own[7], ull m[7]) {
    ull p0[7], p1[7], p2[7];
    ld7(sRed + (0 * Hd + k) * SSTR, p0);
    ld7(sRed + (1 * Hd + k) * SSTR, p1);
    ld7(sRed + (2 * Hd + k) * SSTR, p2);
#pragma unroll
    for (int q = 0; q < 7; ++q) m[q] = add2(add2(own[q], p0[q]), add2(p1[q], p2[q]));
}

// ---------------- merged transpose ----------------
__global__ void transpose_all(const float* __restrict__ wh,
                              const float* __restrict__ wout,
                              const float* __restrict__ wx) {
    __shared__ float tile[32][33];
    int b = blockIdx.x;
    const float* in; float* out; int rows, cols, bx;
    if (b < 64)       { in = wh;   out = g_whT;   rows = Hd; cols = Hd;  bx = b; }
    else if (b < 128) { in = wout; out = g_woutT; rows = Hd; cols = Hd;  bx = b - 64; }
    else              { in = wx;   out = g_wxT;   rows = Hd; cols = INd; bx = b - 128; }
    int nbx = cols / 32;
    int c0 = (bx % nbx) * 32, r0 = (bx / nbx) * 32;
    for (int dy = threadIdx.y; dy < 32; dy += 8)
        tile[dy][threadIdx.x] = in[(r0 + dy) * cols + (c0 + threadIdx.x)];
    __syncthreads();
    for (int dy = threadIdx.y; dy < 32; dy += 8)
        out[(c0 + dy) * rows + (r0 + threadIdx.x)] = tile[threadIdx.x][dy];
}

// ---------------- fused vector-field kernel ----------------
__global__ void __launch_bounds__(NTHR, 1)
fused_kernel(const float* __restrict__ hin, const float* __restrict__ xin,
             const float* __restrict__ xdin, const float* __restrict__ b0,
             const float* __restrict__ b1, float* __restrict__ out) {
    extern __shared__ __align__(16) char smem_raw[];
    float* sA = reinterpret_cast<float*>(smem_raw);          // [Hd][PITCH] 20KB
    float* sB = sA + Hd * PITCH;                             // [Hd][PITCH] 20KB
    ull*   sRed = reinterpret_cast<ull*>(sB + Hd * PITCH);   // [3][Hd][SSTR] 60KB

    const int tid  = threadIdx.x;
    const int c    = tid & 127;        // column pair base: owns columns c, c+128
    const int g    = tid >> 7;         // j-group 0..3
    const int row0 = blockIdx.x * ROWS;

    // ---- stage inputs transposed: sA[j][r]=h, sB[i][r]=x, sB[64+i][r]=xdot
    for (int e = tid; e < ROWS * Hd; e += NTHR) {
        int r = e >> 8, j = e & 255;
        sA[j * PITCH + r] = (row0 + r < Bsz) ? hin[(row0 + r) * Hd + j] : 0.f;
    }
    for (int e = tid; e < ROWS * INd; e += NTHR) {
        int r = e >> 6, i = e & 63;
        bool ok = (row0 + r < Bsz);
        sB[i * PITCH + r]         = ok ? xin[(row0 + r) * INd + i]  : 0.f;
        sB[(INd + i) * PITCH + r] = ok ? xdin[(row0 + r) * INd + i] : 0.f;
    }
    __syncthreads();

    // ---- phase 1: l1 = x@wx^T + h@wh^T + b0 ; uu = xdot@wx^T
    ull l1a[7], l1b[7], ua[7], ub[7];
#pragma unroll
    for (int q = 0; q < 7; ++q) { l1a[q]=0; l1b[q]=0; ua[q]=0; ub[q]=0; }
    {
        int i0 = g * 16;
#pragma unroll 4
        for (int i = i0; i < i0 + 16; ++i) {
            float wa = g_wxT[i * Hd + c];
            float wb = g_wxT[i * Hd + c + 128];
            ull wwa = pack2(wa, wa), wwb = pack2(wb, wb);
            Row vx = ldrow(sB + i * PITCH);
            Row vd = ldrow(sB + (INd + i) * PITCH);
#pragma unroll
            for (int q = 0; q < 7; ++q) {
                l1a[q] = fma2(wwa, vx.v[q], l1a[q]);
                l1b[q] = fma2(wwb, vx.v[q], l1b[q]);
                ua[q]  = fma2(wwa, vd.v[q], ua[q]);
                ub[q]  = fma2(wwb, vd.v[q], ub[q]);
            }
        }
    }
    gemm2(g_whT, c, sA, g * 64, g * 64 + 64, l1a, l1b);

    ull gate[7], dth[7], hdot[7];
    export_partials(sRed, c, g, l1a, l1b);
    __syncthreads();
    if (tid < Hd) {
        ull m[7];
        merge3(sRed, tid, (tid < 128) ? l1a : l1b, m);
        float b0k = b0[tid];
        ull b0p = pack2(b0k, b0k);
        ull relu[7];
#pragma unroll
        for (int q = 0; q < 7; ++q) {
            m[q] = add2(m[q], b0p);
            float a, bb; unpack2(m[q], a, bb);
            float ga = (a  > 0.f) ? 1.f : 0.f;
            float gb = (bb > 0.f) ? 1.f : 0.f;
            gate[q] = pack2(ga, gb);
            relu[q] = pack2(ga * a, gb * bb);
        }
        strow(sB + tid * PITCH, relu);
    }
    __syncthreads();
    export_partials(sRed, c, g, ua, ub);
    __syncthreads();
    if (tid < Hd) {
        ull m[7], gu[7];
        merge3(sRed, tid, (tid < 128) ? ua : ub, m);
#pragma unroll
        for (int q = 0; q < 7; ++q) gu[q] = mul2(m[q], gate[q]);
        strow(sA + tid * PITCH, gu);
    }
    __syncthreads();

    // ---- phase 2: lout = relu@wout^T + b1 ; jx = (g*u)@wout^T
    ull loa[7], lob[7], jxa[7], jxb[7];
#pragma unroll
    for (int q = 0; q < 7; ++q) { loa[q]=0; lob[q]=0; jxa[q]=0; jxb[q]=0; }
    {
        int j0 = g * 64, j1 = j0 + 64;
#pragma unroll 4
        for (int j = j0; j < j1; ++j) {
            float wa = g_woutT[j * Hd + c];
            float wb = g_woutT[j * Hd + c + 128];
            ull wwa = pack2(wa, wa), wwb = pack2(wb, wb);
            Row vr = ldrow(sB + j * PITCH);
            Row vg = ldrow(sA + j * PITCH);
#pragma unroll
            for (int q = 0; q < 7; ++q) {
                loa[q] = fma2(wwa, vr.v[q], loa[q]);
                lob[q] = fma2(wwb, vr.v[q], lob[q]);
                jxa[q] = fma2(wwa, vg.v[q], jxa[q]);
                jxb[q] = fma2(wwb, vg.v[q], jxb[q]);
            }
        }
    }
    export_partials(sRed, c, g, loa, lob);
    __syncthreads();
    if (tid < Hd) {
        ull m[7];
        merge3(sRed, tid, (tid < 128) ? loa : lob, m);
        float b1k = b1[tid];
        ull bp = pack2(b1k, b1k);
#pragma unroll
        for (int q = 0; q < 7; ++q) {
            ull L = add2(m[q], bp);
            float a, bb; unpack2(L, a, bb);
            float ta = tanhf(a), tb = tanhf(bb);
            dth[q] = pack2(1.f - ta * ta, 1.f - tb * tb);
        }
    }
    __syncthreads();
    export_partials(sRed, c, g, jxa, jxb);
    __syncthreads();
    if (tid < Hd) {
        ull m[7], cur[7];
        merge3(sRed, tid, (tid < 128) ? jxa : jxb, m);
#pragma unroll
        for (int q = 0; q < 7; ++q) {
            cur[q] = mul2(m[q], dth[q]);
            hdot[q] = cur[q];
        }
        strow(sA + tid * PITCH, cur);
    }
    __syncthreads();

    // ---- 8 Jh-power iterations: curr = dtanh * ((gate * (curr@wh^T)) @ wout^T)
    for (int it = 0; it < KTERMS; ++it) {
        ull accA[7], accB[7];
#pragma unroll
        for (int q = 0; q < 7; ++q) { accA[q]=0; accB[q]=0; }
        gemm2(g_whT, c, sA, g * 64, g * 64 + 64, accA, accB);
        export_partials(sRed, c, g, accA, accB);
        __syncthreads();
        if (tid < Hd) {
            ull m[7], gt[7];
            merge3(sRed, tid, (tid < 128) ? accA : accB, m);
#pragma unroll
            for (int q = 0; q < 7; ++q) gt[q] = mul2(m[q], gate[q]);
            strow(sB + tid * PITCH, gt);
        }
        __syncthreads();
#pragma unroll
        for (int q = 0; q < 7; ++q) { accA[q]=0; accB[q]=0; }
        gemm2(g_woutT, c, sB, g * 64, g * 64 + 64, accA, accB);
        export_partials(sRed, c, g, accA, accB);
        __syncthreads();
        if (tid < Hd) {
            ull m[7], cur[7];
            merge3(sRed, tid, (tid < 128) ? accA : accB, m);
#pragma unroll
            for (int q = 0; q < 7; ++q) {
                cur[q] = mul2(m[q], dth[q]);
                hdot[q] = add2(hdot[q], cur[q]);
            }
            strow(sA + tid * PITCH, cur);
        }
        __syncthreads();
    }

    // ---- write h_dot (owner threads, coalesced in k; guard tail rows)
    if (tid < Hd) {
#pragma unroll
        for (int q = 0; q < 7; ++q) {
            float a, bb; unpack2(hdot[q], a, bb);
            int r = row0 + 2 * q;
            if (r < Bsz)     out[r       * Hd + tid] = a;
            if (r + 1 < Bsz) out[(r + 1) * Hd + tid] = bb;
        }
    }
}

#define SMEM_BYTES (2 * Hd * PITCH * 4 + 3 * Hd * SSTR * 8)

extern "C" void kernel_launch(void* const* d_in, const int* in_sizes, int n_in,
                              void* d_out, int out_size) {
    (void)in_sizes; (void)n_in; (void)out_size;
    const float* h_   = (const float*)d_in[0];
    const float* x    = (const float*)d_in[1];
    const float* xdot = (const float*)d_in[2];
    const float* wx   = (const float*)d_in[3];
    const float* wh   = (const float*)d_in[4];
    const float* wout = (const float*)d_in[5];
    const float* b0   = (const float*)d_in[6];
    const float* b1   = (const float*)d_in[7];
    float* out = (float*)d_out;

    cudaFuncSetAttribute(fused_kernel, cudaFuncAttributeMaxDynamicSharedMemorySize, SMEM_BYTES);
    transpose_all<<<144, dim3(32, 8)>>>(wh, wout, wx);
    fused_kernel<<<NCTAS, NTHR, SMEM_BYTES>>>(h_, x, xdot, b0, b1, out);
}